// round 16
// baseline (speedup 1.0000x reference)
#include <cuda_runtime.h>
#include <cuda_fp16.h>
#include <math.h>

// Problem constants (fixed by the dataset)
#define N_NODES  20000
#define N_EDGES  320000
#define N_TOT    340000      // edges + self loops
#define N_GRAPHS 512
#define H1  10
#define C1  78
#define F1  780              // H1*C1
#define F1P 784              // padded row stride (16B-aligned, = 7*112)
#define C2  100
#define NEG 0.2f

// ---------------- scratch (device globals; no allocation allowed) ------------
__device__ __align__(16) __half d_h1[N_NODES * F1P];     // x @ W1 (fp16, padded)
__device__ __align__(16) __half d_agg1h[N_NODES * F1P];  // elu(gat1 out) (fp16, padded)
__device__ float d_as1[N_NODES * H1];
__device__ float d_ad1[N_NODES * H1];
__device__ __align__(16) float d_h2[N_NODES * C2];       // agg1 @ W2 (fp32)
__device__ float d_as2[N_NODES];
__device__ float d_ad2[N_NODES];
__device__ int   d_g[N_GRAPHS * C2];        // pooled max (float bits, vals >= 0)
__device__ int   d_cnt[N_NODES + 1];
__device__ int   d_ptr[N_NODES + 1];
__device__ int   d_cur[N_NODES];
__device__ int   d_srcs[N_TOT];             // CSR (by dst) source node ids
__device__ int   d_is64;                    // 1 if index inputs are int64

__device__ __forceinline__ int ld_idx(const int* __restrict__ p, int i) {
    return d_is64 ? p[2 * i] : p[i];
}
__device__ __forceinline__ float lrelu(float v) { return v > 0.f ? v : NEG * v; }

// mma.sync m16n8k16 fp16 inputs, fp32 accum (D += A*B)
__device__ __forceinline__ void mma16816(float* d, const unsigned* a, const unsigned* b) {
    asm volatile(
        "mma.sync.aligned.m16n8k16.row.col.f32.f16.f16.f32 "
        "{%0,%1,%2,%3}, {%4,%5,%6,%7}, {%8,%9}, {%0,%1,%2,%3};\n"
        : "+f"(d[0]), "+f"(d[1]), "+f"(d[2]), "+f"(d[3])
        : "r"(a[0]), "r"(a[1]), "r"(a[2]), "r"(a[3]), "r"(b[0]), "r"(b[1]));
}

// ---------------- dtype detection --------------------------------------------
__global__ void k_detect(const int* __restrict__ ei32) {
    __shared__ int nz;
    if (threadIdx.x == 0) nz = 0;
    __syncthreads();
    int idx = 2 * (threadIdx.x * 1237 + 11) + 1;
    if (ei32[idx] != 0) atomicOr(&nz, 1);
    __syncthreads();
    if (threadIdx.x == 0) d_is64 = nz ? 0 : 1;
}

// ---------------- CSR build --------------------------------------------------
__global__ void k_zero() {
    int i = blockIdx.x * blockDim.x + threadIdx.x;
    if (i <= N_NODES)       d_cnt[i] = 0;
    if (i < N_GRAPHS * C2)  d_g[i] = 0;
}

// zero alpha-dot accumulators (main stream, before gemm1's atomic epilogue)
__global__ void k_zero0() {
    int i = blockIdx.x * blockDim.x + threadIdx.x;
    if (i < N_NODES * H1) { d_as1[i] = 0.f; d_ad1[i] = 0.f; }
}

__global__ void k_count(const int* __restrict__ ei) {
    int e = blockIdx.x * blockDim.x + threadIdx.x;
    if (e >= N_TOT) return;
    int dst = (e < N_EDGES) ? ld_idx(ei, N_EDGES + e) : (e - N_EDGES);
    atomicAdd(&d_cnt[dst], 1);
}

// scan with coalesced smem staging (80 KB dynamic smem)
__global__ void k_scan() {
    extern __shared__ int sc[];
    __shared__ int warpsum[32];
    int t = threadIdx.x;
    int lane = t & 31, wp = t >> 5;
    for (int i = t; i < N_NODES; i += 1024) sc[i] = d_cnt[i];
    __syncthreads();
    int base = t * 20;
    int loc[20];
    int p = 0;
    #pragma unroll
    for (int i = 0; i < 20; i++) {
        int idx = base + i;
        int v = (idx < N_NODES) ? sc[idx] : 0;
        loc[i] = p;
        p += v;
    }
    int inc = p;
    #pragma unroll
    for (int o = 1; o < 32; o <<= 1) {
        int v = __shfl_up_sync(0xffffffffu, inc, o);
        if (lane >= o) inc += v;
    }
    if (lane == 31) warpsum[wp] = inc;
    __syncthreads();
    if (wp == 0) {
        int v = warpsum[lane];
        int iv = v;
        #pragma unroll
        for (int o = 1; o < 32; o <<= 1) {
            int u = __shfl_up_sync(0xffffffffu, iv, o);
            if (lane >= o) iv += u;
        }
        warpsum[lane] = iv - v;
    }
    __syncthreads();
    int off = warpsum[wp] + (inc - p);
    #pragma unroll
    for (int i = 0; i < 20; i++) {
        int idx = base + i;
        if (idx < N_NODES) {
            int val = off + loc[i];
            d_ptr[idx] = val;
            d_cur[idx] = val;
        }
    }
    if (t == 1023) d_ptr[N_NODES] = warpsum[31] + inc;
}

__global__ void k_scatter(const int* __restrict__ ei) {
    int e = blockIdx.x * blockDim.x + threadIdx.x;
    if (e >= N_TOT) return;
    int src, dst;
    if (e < N_EDGES) { src = ld_idx(ei, e); dst = ld_idx(ei, N_EDGES + e); }
    else             { src = dst = e - N_EDGES; }
    int pos = atomicAdd(&d_cur[dst], 1);
    d_srcs[pos] = src;
}

// ---------------- layer 1 GEMM: HMMA + fused alpha1 dots ---------------------
// grid (ceil(N/64), 13), block 256 (8 warps, 4Mx2N)
__global__ void k_gemm1(const float* __restrict__ x, const float* __restrict__ W1,
                        const float* __restrict__ a_src1, const float* __restrict__ a_dst1) {
    __shared__ __half As[64][88];   // [row][k], k padded 78->80
    __shared__ __half Bs[64][88];   // [n][k] n-major
    int n0 = blockIdx.x * 64, g0 = blockIdx.y * 64;
    int t = threadIdx.x;

    for (int idx = t; idx < 64 * 80; idx += 256) {
        int r = idx / 80, c = idx - r * 80;
        int node = n0 + r;
        float v = (node < N_NODES && c < 78) ? x[node * 78 + c] : 0.f;
        As[r][c] = __float2half_rn(v);
    }
    for (int idx = t; idx < 64 * 80; idx += 256) {
        int n = idx & 63, k = idx >> 6;
        int col = g0 + n;
        float v = (col < F1 && k < 78) ? W1[k * F1 + col] : 0.f;   // pad cols -> 0
        Bs[n][k] = __float2half_rn(v);
    }
    __syncthreads();

    int wid = t >> 5, lane = t & 31;
    int wm = wid & 3, wn = wid >> 2;
    int r = wm * 16 + (lane >> 2);
    int qc = (lane & 3) * 2;
    float d[4][4] = {};
    #pragma unroll
    for (int ks = 0; ks < 5; ks++) {
        int kb = ks * 16;
        unsigned a[4];
        a[0] = *(const unsigned*)&As[r][kb + qc];
        a[1] = *(const unsigned*)&As[r + 8][kb + qc];
        a[2] = *(const unsigned*)&As[r][kb + qc + 8];
        a[3] = *(const unsigned*)&As[r + 8][kb + qc + 8];
        #pragma unroll
        for (int j = 0; j < 4; j++) {
            int n = wn * 32 + j * 8 + (lane >> 2);
            unsigned b[2];
            b[0] = *(const unsigned*)&Bs[n][kb + qc];
            b[1] = *(const unsigned*)&Bs[n][kb + 8 + qc];
            mma16816(d[j], a, b);
        }
    }

    int node0 = n0 + r;
    // store h1 + accumulate alpha partial dots (col even; pair never straddles a head)
    float pa[2][2][2] = {};          // [slot][row0/row8][src/dst]
    int hd[2] = { -1, -1 };
    #pragma unroll
    for (int j = 0; j < 4; j++) {
        int col = g0 + wn * 32 + j * 8 + qc;
        if (col < F1P) {
            if (node0 < N_NODES) {
                __half2 h = __floats2half2_rn(d[j][0], d[j][1]);
                *(__half2*)&d_h1[(size_t)node0 * F1P + col] = h;
            }
            if (node0 + 8 < N_NODES) {
                __half2 h = __floats2half2_rn(d[j][2], d[j][3]);
                *(__half2*)&d_h1[(size_t)(node0 + 8) * F1P + col] = h;
            }
        }
        if (col < F1) {
            int h = col / C1;
            int slot = (hd[0] < 0 || hd[0] == h) ? 0 : 1;
            hd[slot] = h;
            float a0 = a_src1[col], a1v = a_src1[col + 1];
            float b0 = a_dst1[col], b1v = a_dst1[col + 1];
            pa[slot][0][0] += d[j][0] * a0 + d[j][1] * a1v;
            pa[slot][0][1] += d[j][0] * b0 + d[j][1] * b1v;
            pa[slot][1][0] += d[j][2] * a0 + d[j][3] * a1v;
            pa[slot][1][1] += d[j][2] * b0 + d[j][3] * b1v;
        }
    }
    #pragma unroll
    for (int slot = 0; slot < 2; slot++) {
        if (hd[slot] >= 0) {
            if (node0 < N_NODES) {
                atomicAdd(&d_as1[node0 * H1 + hd[slot]], pa[slot][0][0]);
                atomicAdd(&d_ad1[node0 * H1 + hd[slot]], pa[slot][0][1]);
            }
            if (node0 + 8 < N_NODES) {
                atomicAdd(&d_as1[(node0 + 8) * H1 + hd[slot]], pa[slot][1][0]);
                atomicAdd(&d_ad1[(node0 + 8) * H1 + hd[slot]], pa[slot][1][1]);
            }
        }
    }
}

// GAT layer-1: fused softmax (no max shift; logits O(5)) + gather + bias + elu.
// One block (128 thr) per node; uint4 gathers; normalize in epilogue.
__global__ void k_agg1(const float* __restrict__ b1) {
    __shared__ float s_w[64 * H1];
    __shared__ int   s_src[64];
    __shared__ float s_ad[H1], s_den[H1], s_inv[H1];
    int n = blockIdx.x, t = threadIdx.x;
    int beg = d_ptr[n], end = d_ptr[n + 1];
    if (t < H1) { s_ad[t] = d_ad1[n * H1 + t]; s_den[t] = 0.f; }

    int c8 = 8 * t;                       // t < 98 active (98*8 = 784)
    int hlo = c8 / C1;
    int nlo = min(C1 * (hlo + 1) - c8, 8);   // j < nlo -> head hlo
    int hhi = min((c8 + 7) / C1, H1 - 1);
    float acc[8] = {};

    for (int base = beg; base < end; base += 64) {
        int nl = min(64, end - base);
        __syncthreads();                       // prev s_w consumed / init visible
        if (t < nl) s_src[t] = d_srcs[base + t];
        __syncthreads();
        for (int item = t; item < nl * H1; item += 128) {
            int el = item / H1, h = item - el * H1;
            float w = expf(lrelu(d_as1[s_src[el] * H1 + h] + s_ad[h]));
            s_w[item] = w;
            atomicAdd(&s_den[h], w);
        }
        __syncthreads();
        if (t < 98) {
            #pragma unroll 2
            for (int el = 0; el < nl; el++) {
                uint4 u = *(const uint4*)(d_h1 + (size_t)s_src[el] * F1P + c8);
                const float* wr = s_w + el * H1;
                float wlo = wr[hlo], whi = wr[hhi];
                float2 f0 = __half22float2(*reinterpret_cast<__half2*>(&u.x));
                float2 f1 = __half22float2(*reinterpret_cast<__half2*>(&u.y));
                float2 f2 = __half22float2(*reinterpret_cast<__half2*>(&u.z));
                float2 f3 = __half22float2(*reinterpret_cast<__half2*>(&u.w));
                acc[0] += f0.x * (0 < nlo ? wlo : whi);
                acc[1] += f0.y * (1 < nlo ? wlo : whi);
                acc[2] += f1.x * (2 < nlo ? wlo : whi);
                acc[3] += f1.y * (3 < nlo ? wlo : whi);
                acc[4] += f2.x * (4 < nlo ? wlo : whi);
                acc[5] += f2.y * (5 < nlo ? wlo : whi);
                acc[6] += f3.x * (6 < nlo ? wlo : whi);
                acc[7] += f3.y * (7 < nlo ? wlo : whi);
            }
        }
    }
    __syncthreads();
    if (t < H1) s_inv[t] = 1.f / (s_den[t] + 1e-16f);
    __syncthreads();
    if (t < 98) {
        float ilo = s_inv[hlo], ihi = s_inv[hhi];
        float o[8];
        #pragma unroll
        for (int j = 0; j < 8; j++) {
            int c = c8 + j;
            if (c < F1) {
                float v = acc[j] * (j < nlo ? ilo : ihi) + b1[c];
                o[j] = v > 0.f ? v : expm1f(v);
            } else o[j] = 0.f;               // zero padding (cols 780-783)
        }
        __half2 h0 = __floats2half2_rn(o[0], o[1]);
        __half2 h1 = __floats2half2_rn(o[2], o[3]);
        __half2 h2 = __floats2half2_rn(o[4], o[5]);
        __half2 h3 = __floats2half2_rn(o[6], o[7]);
        uint4 u;
        u.x = *(unsigned*)&h0; u.y = *(unsigned*)&h1;
        u.z = *(unsigned*)&h2; u.w = *(unsigned*)&h3;
        *(uint4*)(d_agg1h + (size_t)n * F1P + c8) = u;
    }
}

// ---------------- layer 2 GEMM: HMMA + fused alpha2 --------------------------
// grid ceil(N/64), block 256 (8 warps, 4Mx2N), K tiles of 112 (784 = 7*112)
__global__ void k_gemm2(const float* __restrict__ W2,
                        const float* __restrict__ a_src2, const float* __restrict__ a_dst2) {
    __shared__ __half As[64][120];
    __shared__ __half Bs[112][120];
    __shared__ float sds[64][2];
    int n0 = blockIdx.x * 64;
    int t = threadIdx.x;
    int wid = t >> 5, lane = t & 31;
    int wm = wid & 3, wn = wid >> 2;
    int r = wm * 16 + (lane >> 2);
    int qc = (lane & 3) * 2;
    float d[7][4] = {};
    if (t < 64) { sds[t][0] = 0.f; sds[t][1] = 0.f; }

    for (int kt = 0; kt < 7; kt++) {
        int k0 = kt * 112;
        __syncthreads();
        for (int idx = t; idx < 64 * 14; idx += 256) {
            int rr = idx / 14, c8 = (idx - rr * 14) * 8;
            int node = n0 + rr;
            uint4 u = make_uint4(0u, 0u, 0u, 0u);
            if (node < N_NODES)
                u = *(const uint4*)(d_agg1h + (size_t)node * F1P + k0 + c8);
            *(uint4*)&As[rr][c8] = u;
        }
        for (int idx = t; idx < 112 * 112; idx += 256) {
            int n = idx % 112, k = idx / 112;
            float v = (n < C2 && k0 + k < F1) ? W2[(k0 + k) * C2 + n] : 0.f;
            Bs[n][k] = __float2half_rn(v);
        }
        __syncthreads();
        #pragma unroll
        for (int ks = 0; ks < 7; ks++) {
            int kb = ks * 16;
            unsigned a[4];
            a[0] = *(const unsigned*)&As[r][kb + qc];
            a[1] = *(const unsigned*)&As[r + 8][kb + qc];
            a[2] = *(const unsigned*)&As[r][kb + qc + 8];
            a[3] = *(const unsigned*)&As[r + 8][kb + qc + 8];
            #pragma unroll
            for (int j = 0; j < 7; j++) {
                int n = wn * 56 + j * 8 + (lane >> 2);
                unsigned b[2];
                b[0] = *(const unsigned*)&Bs[n][kb + qc];
                b[1] = *(const unsigned*)&Bs[n][kb + 8 + qc];
                mma16816(d[j], a, b);
            }
        }
    }

    // store h2 + fused alpha2 partial dots
    int node0 = n0 + r;
    float ps0 = 0.f, pd0 = 0.f, ps1 = 0.f, pd1 = 0.f;
    #pragma unroll
    for (int j = 0; j < 7; j++) {
        int col = wn * 56 + j * 8 + qc;
        if (col < C2) {
            float as0 = a_src2[col], as1v = a_src2[col + 1];
            float ad0 = a_dst2[col], ad1v = a_dst2[col + 1];
            ps0 += d[j][0] * as0 + d[j][1] * as1v;
            pd0 += d[j][0] * ad0 + d[j][1] * ad1v;
            ps1 += d[j][2] * as0 + d[j][3] * as1v;
            pd1 += d[j][2] * ad0 + d[j][3] * ad1v;
            if (node0 < N_NODES) {
                d_h2[(size_t)node0 * C2 + col]     = d[j][0];
                d_h2[(size_t)node0 * C2 + col + 1] = d[j][1];
            }
            if (node0 + 8 < N_NODES) {
                d_h2[(size_t)(node0 + 8) * C2 + col]     = d[j][2];
                d_h2[(size_t)(node0 + 8) * C2 + col + 1] = d[j][3];
            }
        }
    }
    atomicAdd(&sds[r][0], ps0);
    atomicAdd(&sds[r][1], pd0);
    atomicAdd(&sds[r + 8][0], ps1);
    atomicAdd(&sds[r + 8][1], pd1);
    __syncthreads();
    if (t < 64) {
        int node = n0 + t;
        if (node < N_NODES) {
            d_as2[node] = sds[t][0];
            d_ad2[node] = sds[t][1];
        }
    }
}

// GAT layer-2: fused softmax + gather (float4) + bias + relu + max pool.
// Warp per node, 32-edge chunks; normalize in epilogue.
__global__ void k_agg2(const float* __restrict__ b2, const int* __restrict__ batch) {
    __shared__ float s_w[4][32];
    __shared__ int   s_s[4][32];
    int wp = threadIdx.x >> 5;
    int n = blockIdx.x * 4 + wp;
    if (n >= N_NODES) return;
    int lane = threadIdx.x & 31;
    int beg = d_ptr[n], end = d_ptr[n + 1];
    float ad = d_ad2[n];
    int c4 = lane * 4;                         // lane < 25 active in gather

    float den = 0.f;
    float4 acc = make_float4(0.f, 0.f, 0.f, 0.f);
    for (int base = beg; base < end; base += 32) {
        int nl = min(32, end - base);
        __syncwarp();
        if (lane < nl) {
            int s = d_srcs[base + lane];
            s_s[wp][lane] = s;
            float w = expf(lrelu(d_as2[s] + ad));
            s_w[wp][lane] = w;
            den += w;
        }
        __syncwarp();
        if (lane < 25) {
            #pragma unroll 2
            for (int e = 0; e < nl; e++) {
                float w = s_w[wp][e];
                float4 v = *(const float4*)(d_h2 + (size_t)s_s[wp][e] * C2 + c4);
                acc.x += w * v.x;
                acc.y += w * v.y;
                acc.z += w * v.z;
                acc.w += w * v.w;
            }
        }
    }
    #pragma unroll
    for (int o = 16; o; o >>= 1) den += __shfl_xor_sync(0xffffffffu, den, o);
    float inv = 1.f / (den + 1e-16f);
    if (lane < 25) {
        int b = ld_idx(batch, n);
        float v;
        v = fmaxf(acc.x * inv + b2[c4], 0.f);
        atomicMax(&d_g[b * C2 + c4], __float_as_int(v));
        v = fmaxf(acc.y * inv + b2[c4 + 1], 0.f);
        atomicMax(&d_g[b * C2 + c4 + 1], __float_as_int(v));
        v = fmaxf(acc.z * inv + b2[c4 + 2], 0.f);
        atomicMax(&d_g[b * C2 + c4 + 2], __float_as_int(v));
        v = fmaxf(acc.w * inv + b2[c4 + 3], 0.f);
        atomicMax(&d_g[b * C2 + c4 + 3], __float_as_int(v));
    }
}

// ---------------- head -------------------------------------------------------
__global__ void k_final(const float* __restrict__ Wg, const float* __restrict__ bg,
                        float* __restrict__ out) {
    __shared__ float sg[C2];
    int g = blockIdx.x, t = threadIdx.x;
    if (t < C2) sg[t] = __int_as_float(d_g[g * C2 + t]);
    __syncthreads();
    if (t < C2) {
        float a = bg[t];
        #pragma unroll 4
        for (int k = 0; k < C2; k++) a += sg[k] * Wg[k * C2 + t];
        out[g * C2 + t] = fmaxf(a, 0.f);
    }
}

// ---------------- launch ------------------------------------------------------
extern "C" void kernel_launch(void* const* d_in, const int* in_sizes, int n_in,
                              void* d_out, int out_size) {
    const float* x     = (const float*)d_in[0];
    const int*   ei    = (const int*)d_in[1];
    const int*   batch = (const int*)d_in[2];

    int base = 3;
    while (base < n_in && in_sizes[base] != 78 * F1) base++;
    if (base >= n_in) base = (n_in >= 14) ? 4 : 3;

    const float* W1     = (const float*)d_in[base + 0];
    const float* a_src1 = (const float*)d_in[base + 1];
    const float* a_dst1 = (const float*)d_in[base + 2];
    const float* b1     = (const float*)d_in[base + 3];
    const float* W2     = (const float*)d_in[base + 4];
    const float* a_src2 = (const float*)d_in[base + 5];
    const float* a_dst2 = (const float*)d_in[base + 6];
    const float* b2     = (const float*)d_in[base + 7];
    const float* Wg     = (const float*)d_in[base + 8];
    const float* bg     = (const float*)d_in[base + 9];
    float* out = (float*)d_out;

    static bool s_init = false;
    static cudaStream_t s1;
    static cudaEvent_t ev0, ev1;
    if (!s_init) {
        cudaStreamCreateWithFlags(&s1, cudaStreamNonBlocking);
        cudaEventCreateWithFlags(&ev0, cudaEventDisableTiming);
        cudaEventCreateWithFlags(&ev1, cudaEventDisableTiming);
        cudaFuncSetAttribute(k_scan, cudaFuncAttributeMaxDynamicSharedMemorySize,
                             N_NODES * (int)sizeof(int) + 128);
        s_init = true;
    }

    cudaEventRecord(ev0, 0);
    cudaStreamWaitEvent(s1, ev0, 0);
    k_detect <<<1, 256, 0, s1>>>(ei);
    k_zero   <<<(N_GRAPHS * C2 + 255) / 256, 256, 0, s1>>>();
    k_count  <<<(N_TOT + 255) / 256, 256, 0, s1>>>(ei);
    k_scan   <<<1, 1024, N_NODES * sizeof(int), s1>>>();
    k_scatter<<<(N_TOT + 255) / 256, 256, 0, s1>>>(ei);
    cudaEventRecord(ev1, s1);

    k_zero0<<<(N_NODES * H1 + 255) / 256, 256>>>();      // before gemm1 atomics
    dim3 g1((N_NODES + 63) / 64, (F1P + 63) / 64);
    k_gemm1<<<g1, 256>>>(x, W1, a_src1, a_dst1);

    cudaStreamWaitEvent(0, ev1, 0);                      // join CSR before agg1
    k_agg1<<<N_NODES, 128>>>(b1);

    k_gemm2<<<(N_NODES + 63) / 64, 256>>>(W2, a_src2, a_dst2);
    k_agg2 <<<(N_NODES + 3) / 4, 128>>>(b2, batch);

    k_final<<<N_GRAPHS, 128>>>(Wg, bg, out);
}

// round 17
// speedup vs baseline: 1.1066x; 1.1066x over previous
#include <cuda_runtime.h>
#include <cuda_fp16.h>
#include <math.h>

// Problem constants (fixed by the dataset)
#define N_NODES  20000
#define N_EDGES  320000
#define N_TOT    340000      // edges + self loops
#define N_GRAPHS 512
#define H1  10
#define C1  78
#define F1  780              // H1*C1
#define F1P 784              // padded row stride (16B-aligned, = 7*112)
#define C2  100
#define NEG 0.2f

// ---------------- scratch (device globals; no allocation allowed) ------------
__device__ __align__(16) __half d_h1[N_NODES * F1P];     // x @ W1 (fp16, padded)
__device__ __align__(16) __half d_agg1h[N_NODES * F1P];  // elu(gat1 out) (fp16, padded)
__device__ float d_as1[N_NODES * H1];
__device__ float d_ad1[N_NODES * H1];
__device__ __align__(16) float d_h2[N_NODES * C2];       // agg1 @ W2 (fp32)
__device__ float d_as2[N_NODES];
__device__ float d_ad2[N_NODES];
__device__ int   d_g[N_GRAPHS * C2];        // pooled max (float bits, vals >= 0)
__device__ int   d_cnt[N_NODES + 1];
__device__ int   d_ptr[N_NODES + 1];
__device__ int   d_cur[N_NODES];
__device__ int   d_bsum[20];                // per-block sums for 2-phase scan
__device__ int   d_srcs[N_TOT];             // CSR (by dst) source node ids
__device__ int   d_is64;                    // 1 if index inputs are int64

__device__ __forceinline__ int ld_idx(const int* __restrict__ p, int i) {
    return d_is64 ? p[2 * i] : p[i];
}
__device__ __forceinline__ float lrelu(float v) { return v > 0.f ? v : NEG * v; }

// mma.sync m16n8k16 fp16 inputs, fp32 accum (D += A*B)
__device__ __forceinline__ void mma16816(float* d, const unsigned* a, const unsigned* b) {
    asm volatile(
        "mma.sync.aligned.m16n8k16.row.col.f32.f16.f16.f32 "
        "{%0,%1,%2,%3}, {%4,%5,%6,%7}, {%8,%9}, {%0,%1,%2,%3};\n"
        : "+f"(d[0]), "+f"(d[1]), "+f"(d[2]), "+f"(d[3])
        : "r"(a[0]), "r"(a[1]), "r"(a[2]), "r"(a[3]), "r"(b[0]), "r"(b[1]));
}

// ---------------- dtype detection --------------------------------------------
__global__ void k_detect(const int* __restrict__ ei32) {
    __shared__ int nz;
    if (threadIdx.x == 0) nz = 0;
    __syncthreads();
    int idx = 2 * (threadIdx.x * 1237 + 11) + 1;
    if (ei32[idx] != 0) atomicOr(&nz, 1);
    __syncthreads();
    if (threadIdx.x == 0) d_is64 = nz ? 0 : 1;
}

// ---------------- CSR build --------------------------------------------------
__global__ void k_zero() {
    int i = blockIdx.x * blockDim.x + threadIdx.x;
    if (i <= N_NODES)       d_cnt[i] = 0;
    if (i < N_GRAPHS * C2)  d_g[i] = 0;
}

// zero alpha-dot accumulators (main stream, before gemm1's atomic epilogue)
__global__ void k_zero0() {
    int i = blockIdx.x * blockDim.x + threadIdx.x;
    if (i < N_NODES * H1) { d_as1[i] = 0.f; d_ad1[i] = 0.f; }
}

__global__ void k_count(const int* __restrict__ ei) {
    int e = blockIdx.x * blockDim.x + threadIdx.x;
    if (e >= N_TOT) return;
    int dst = (e < N_EDGES) ? ld_idx(ei, N_EDGES + e) : (e - N_EDGES);
    atomicAdd(&d_cnt[dst], 1);
}

// 2-phase multi-block scan: phase A = block-local exclusive prefix + block sum.
// 20 blocks x 1024 threads, block b covers nodes [b*1000, b*1000+1000).
__global__ void k_scanA() {
    __shared__ int warpsum[32];
    int b = blockIdx.x, t = threadIdx.x;
    int lane = t & 31, wp = t >> 5;
    int idx = b * 1000 + t;
    int v = (t < 1000) ? d_cnt[idx] : 0;
    int inc = v;
    #pragma unroll
    for (int o = 1; o < 32; o <<= 1) {
        int u = __shfl_up_sync(0xffffffffu, inc, o);
        if (lane >= o) inc += u;
    }
    if (lane == 31) warpsum[wp] = inc;
    __syncthreads();
    if (wp == 0) {
        int v0 = warpsum[lane];
        int iv = v0;
        #pragma unroll
        for (int o = 1; o < 32; o <<= 1) {
            int u = __shfl_up_sync(0xffffffffu, iv, o);
            if (lane >= o) iv += u;
        }
        warpsum[lane] = iv - v0;            // exclusive warp offsets
        if (lane == 31) d_bsum[b] = iv;     // block total
    }
    __syncthreads();
    if (t < 1000) d_ptr[idx] = warpsum[wp] + (inc - v);   // local exclusive
}

// phase C: add block offsets; block 19 also writes the grand total.
__global__ void k_scanC() {
    __shared__ int soff;
    int b = blockIdx.x, t = threadIdx.x;
    if (t == 0) {
        int off = 0;
        #pragma unroll 4
        for (int j = 0; j < 20; j++) if (j < b) off += d_bsum[j];
        soff = off;
        if (b == 19) d_ptr[N_NODES] = off + d_bsum[19];
    }
    __syncthreads();
    int idx = b * 1000 + t;
    if (t < 1000) {
        int val = d_ptr[idx] + soff;
        d_ptr[idx] = val;
        d_cur[idx] = val;
    }
}

__global__ void k_scatter(const int* __restrict__ ei) {
    int e = blockIdx.x * blockDim.x + threadIdx.x;
    if (e >= N_TOT) return;
    int src, dst;
    if (e < N_EDGES) { src = ld_idx(ei, e); dst = ld_idx(ei, N_EDGES + e); }
    else             { src = dst = e - N_EDGES; }
    int pos = atomicAdd(&d_cur[dst], 1);
    d_srcs[pos] = src;
}

// ---------------- layer 1 GEMM: HMMA + fused alpha1 dots ---------------------
// grid (ceil(N/64), 13), block 256 (8 warps, 4Mx2N)
__global__ void k_gemm1(const float* __restrict__ x, const float* __restrict__ W1,
                        const float* __restrict__ a_src1, const float* __restrict__ a_dst1) {
    __shared__ __half As[64][88];   // [row][k], k padded 78->80
    __shared__ __half Bs[64][88];   // [n][k] n-major
    int n0 = blockIdx.x * 64, g0 = blockIdx.y * 64;
    int t = threadIdx.x;

    for (int idx = t; idx < 64 * 80; idx += 256) {
        int r = idx / 80, c = idx - r * 80;
        int node = n0 + r;
        float v = (node < N_NODES && c < 78) ? x[node * 78 + c] : 0.f;
        As[r][c] = __float2half_rn(v);
    }
    for (int idx = t; idx < 64 * 80; idx += 256) {
        int n = idx & 63, k = idx >> 6;
        int col = g0 + n;
        float v = (col < F1 && k < 78) ? W1[k * F1 + col] : 0.f;   // pad cols -> 0
        Bs[n][k] = __float2half_rn(v);
    }
    __syncthreads();

    int wid = t >> 5, lane = t & 31;
    int wm = wid & 3, wn = wid >> 2;
    int r = wm * 16 + (lane >> 2);
    int qc = (lane & 3) * 2;
    float d[4][4] = {};
    #pragma unroll
    for (int ks = 0; ks < 5; ks++) {
        int kb = ks * 16;
        unsigned a[4];
        a[0] = *(const unsigned*)&As[r][kb + qc];
        a[1] = *(const unsigned*)&As[r + 8][kb + qc];
        a[2] = *(const unsigned*)&As[r][kb + qc + 8];
        a[3] = *(const unsigned*)&As[r + 8][kb + qc + 8];
        #pragma unroll
        for (int j = 0; j < 4; j++) {
            int n = wn * 32 + j * 8 + (lane >> 2);
            unsigned b[2];
            b[0] = *(const unsigned*)&Bs[n][kb + qc];
            b[1] = *(const unsigned*)&Bs[n][kb + 8 + qc];
            mma16816(d[j], a, b);
        }
    }

    int node0 = n0 + r;
    // store h1 + accumulate alpha partial dots (col even; pair never straddles a head)
    float pa[2][2][2] = {};          // [slot][row0/row8][src/dst]
    int hd[2] = { -1, -1 };
    #pragma unroll
    for (int j = 0; j < 4; j++) {
        int col = g0 + wn * 32 + j * 8 + qc;
        if (col < F1P) {
            if (node0 < N_NODES) {
                __half2 h = __floats2half2_rn(d[j][0], d[j][1]);
                *(__half2*)&d_h1[(size_t)node0 * F1P + col] = h;
            }
            if (node0 + 8 < N_NODES) {
                __half2 h = __floats2half2_rn(d[j][2], d[j][3]);
                *(__half2*)&d_h1[(size_t)(node0 + 8) * F1P + col] = h;
            }
        }
        if (col < F1) {
            int h = col / C1;
            int slot = (hd[0] < 0 || hd[0] == h) ? 0 : 1;
            hd[slot] = h;
            float a0 = a_src1[col], a1v = a_src1[col + 1];
            float b0 = a_dst1[col], b1v = a_dst1[col + 1];
            pa[slot][0][0] += d[j][0] * a0 + d[j][1] * a1v;
            pa[slot][0][1] += d[j][0] * b0 + d[j][1] * b1v;
            pa[slot][1][0] += d[j][2] * a0 + d[j][3] * a1v;
            pa[slot][1][1] += d[j][2] * b0 + d[j][3] * b1v;
        }
    }
    #pragma unroll
    for (int slot = 0; slot < 2; slot++) {
        if (hd[slot] >= 0) {
            if (node0 < N_NODES) {
                atomicAdd(&d_as1[node0 * H1 + hd[slot]], pa[slot][0][0]);
                atomicAdd(&d_ad1[node0 * H1 + hd[slot]], pa[slot][0][1]);
            }
            if (node0 + 8 < N_NODES) {
                atomicAdd(&d_as1[(node0 + 8) * H1 + hd[slot]], pa[slot][1][0]);
                atomicAdd(&d_ad1[(node0 + 8) * H1 + hd[slot]], pa[slot][1][1]);
            }
        }
    }
}

// GAT layer-1: fused softmax (no max shift; logits O(5)) + gather + bias + elu.
// One block (128 thr) per node; uint4 gathers; normalize in epilogue.
__global__ void k_agg1(const float* __restrict__ b1) {
    __shared__ float s_w[64 * H1];
    __shared__ int   s_src[64];
    __shared__ float s_ad[H1], s_den[H1], s_inv[H1];
    int n = blockIdx.x, t = threadIdx.x;
    int beg = d_ptr[n], end = d_ptr[n + 1];
    if (t < H1) { s_ad[t] = d_ad1[n * H1 + t]; s_den[t] = 0.f; }

    int c8 = 8 * t;                       // t < 98 active (98*8 = 784)
    int hlo = c8 / C1;
    int nlo = min(C1 * (hlo + 1) - c8, 8);   // j < nlo -> head hlo
    int hhi = min((c8 + 7) / C1, H1 - 1);
    float acc[8] = {};

    for (int base = beg; base < end; base += 64) {
        int nl = min(64, end - base);
        __syncthreads();                       // prev s_w consumed / init visible
        if (t < nl) s_src[t] = d_srcs[base + t];
        __syncthreads();
        for (int item = t; item < nl * H1; item += 128) {
            int el = item / H1, h = item - el * H1;
            float w = expf(lrelu(d_as1[s_src[el] * H1 + h] + s_ad[h]));
            s_w[item] = w;
            atomicAdd(&s_den[h], w);
        }
        __syncthreads();
        if (t < 98) {
            #pragma unroll 2
            for (int el = 0; el < nl; el++) {
                uint4 u = *(const uint4*)(d_h1 + (size_t)s_src[el] * F1P + c8);
                const float* wr = s_w + el * H1;
                float wlo = wr[hlo], whi = wr[hhi];
                float2 f0 = __half22float2(*reinterpret_cast<__half2*>(&u.x));
                float2 f1 = __half22float2(*reinterpret_cast<__half2*>(&u.y));
                float2 f2 = __half22float2(*reinterpret_cast<__half2*>(&u.z));
                float2 f3 = __half22float2(*reinterpret_cast<__half2*>(&u.w));
                acc[0] += f0.x * (0 < nlo ? wlo : whi);
                acc[1] += f0.y * (1 < nlo ? wlo : whi);
                acc[2] += f1.x * (2 < nlo ? wlo : whi);
                acc[3] += f1.y * (3 < nlo ? wlo : whi);
                acc[4] += f2.x * (4 < nlo ? wlo : whi);
                acc[5] += f2.y * (5 < nlo ? wlo : whi);
                acc[6] += f3.x * (6 < nlo ? wlo : whi);
                acc[7] += f3.y * (7 < nlo ? wlo : whi);
            }
        }
    }
    __syncthreads();
    if (t < H1) s_inv[t] = 1.f / (s_den[t] + 1e-16f);
    __syncthreads();
    if (t < 98) {
        float ilo = s_inv[hlo], ihi = s_inv[hhi];
        float o[8];
        #pragma unroll
        for (int j = 0; j < 8; j++) {
            int c = c8 + j;
            if (c < F1) {
                float v = acc[j] * (j < nlo ? ilo : ihi) + b1[c];
                o[j] = v > 0.f ? v : expm1f(v);
            } else o[j] = 0.f;               // zero padding (cols 780-783)
        }
        __half2 h0 = __floats2half2_rn(o[0], o[1]);
        __half2 h1 = __floats2half2_rn(o[2], o[3]);
        __half2 h2 = __floats2half2_rn(o[4], o[5]);
        __half2 h3 = __floats2half2_rn(o[6], o[7]);
        uint4 u;
        u.x = *(unsigned*)&h0; u.y = *(unsigned*)&h1;
        u.z = *(unsigned*)&h2; u.w = *(unsigned*)&h3;
        *(uint4*)(d_agg1h + (size_t)n * F1P + c8) = u;
    }
}

// ---------------- layer 2 GEMM: HMMA + fused alpha2 --------------------------
// grid ceil(N/64), block 256 (8 warps, 4Mx2N), K tiles of 112 (784 = 7*112)
__global__ void k_gemm2(const float* __restrict__ W2,
                        const float* __restrict__ a_src2, const float* __restrict__ a_dst2) {
    __shared__ __half As[64][120];
    __shared__ __half Bs[112][120];
    __shared__ float sds[64][2];
    int n0 = blockIdx.x * 64;
    int t = threadIdx.x;
    int wid = t >> 5, lane = t & 31;
    int wm = wid & 3, wn = wid >> 2;
    int r = wm * 16 + (lane >> 2);
    int qc = (lane & 3) * 2;
    float d[7][4] = {};
    if (t < 64) { sds[t][0] = 0.f; sds[t][1] = 0.f; }

    for (int kt = 0; kt < 7; kt++) {
        int k0 = kt * 112;
        __syncthreads();
        for (int idx = t; idx < 64 * 14; idx += 256) {
            int rr = idx / 14, c8 = (idx - rr * 14) * 8;
            int node = n0 + rr;
            uint4 u = make_uint4(0u, 0u, 0u, 0u);
            if (node < N_NODES)
                u = *(const uint4*)(d_agg1h + (size_t)node * F1P + k0 + c8);
            *(uint4*)&As[rr][c8] = u;
        }
        for (int idx = t; idx < 112 * 112; idx += 256) {
            int n = idx % 112, k = idx / 112;
            float v = (n < C2 && k0 + k < F1) ? W2[(k0 + k) * C2 + n] : 0.f;
            Bs[n][k] = __float2half_rn(v);
        }
        __syncthreads();
        #pragma unroll
        for (int ks = 0; ks < 7; ks++) {
            int kb = ks * 16;
            unsigned a[4];
            a[0] = *(const unsigned*)&As[r][kb + qc];
            a[1] = *(const unsigned*)&As[r + 8][kb + qc];
            a[2] = *(const unsigned*)&As[r][kb + qc + 8];
            a[3] = *(const unsigned*)&As[r + 8][kb + qc + 8];
            #pragma unroll
            for (int j = 0; j < 7; j++) {
                int n = wn * 56 + j * 8 + (lane >> 2);
                unsigned b[2];
                b[0] = *(const unsigned*)&Bs[n][kb + qc];
                b[1] = *(const unsigned*)&Bs[n][kb + 8 + qc];
                mma16816(d[j], a, b);
            }
        }
    }

    // store h2 + fused alpha2 partial dots
    int node0 = n0 + r;
    float ps0 = 0.f, pd0 = 0.f, ps1 = 0.f, pd1 = 0.f;
    #pragma unroll
    for (int j = 0; j < 7; j++) {
        int col = wn * 56 + j * 8 + qc;
        if (col < C2) {
            float as0 = a_src2[col], as1v = a_src2[col + 1];
            float ad0 = a_dst2[col], ad1v = a_dst2[col + 1];
            ps0 += d[j][0] * as0 + d[j][1] * as1v;
            pd0 += d[j][0] * ad0 + d[j][1] * ad1v;
            ps1 += d[j][2] * as0 + d[j][3] * as1v;
            pd1 += d[j][2] * ad0 + d[j][3] * ad1v;
            if (node0 < N_NODES) {
                d_h2[(size_t)node0 * C2 + col]     = d[j][0];
                d_h2[(size_t)node0 * C2 + col + 1] = d[j][1];
            }
            if (node0 + 8 < N_NODES) {
                d_h2[(size_t)(node0 + 8) * C2 + col]     = d[j][2];
                d_h2[(size_t)(node0 + 8) * C2 + col + 1] = d[j][3];
            }
        }
    }
    atomicAdd(&sds[r][0], ps0);
    atomicAdd(&sds[r][1], pd0);
    atomicAdd(&sds[r + 8][0], ps1);
    atomicAdd(&sds[r + 8][1], pd1);
    __syncthreads();
    if (t < 64) {
        int node = n0 + t;
        if (node < N_NODES) {
            d_as2[node] = sds[t][0];
            d_ad2[node] = sds[t][1];
        }
    }
}

// GAT layer-2: fused softmax + gather (float4) + bias + relu + max pool.
// Warp per node, 32-edge chunks; normalize in epilogue.
__global__ void k_agg2(const float* __restrict__ b2, const int* __restrict__ batch) {
    __shared__ float s_w[4][32];
    __shared__ int   s_s[4][32];
    int wp = threadIdx.x >> 5;
    int n = blockIdx.x * 4 + wp;
    if (n >= N_NODES) return;
    int lane = threadIdx.x & 31;
    int beg = d_ptr[n], end = d_ptr[n + 1];
    float ad = d_ad2[n];
    int c4 = lane * 4;                         // lane < 25 active in gather

    float den = 0.f;
    float4 acc = make_float4(0.f, 0.f, 0.f, 0.f);
    for (int base = beg; base < end; base += 32) {
        int nl = min(32, end - base);
        __syncwarp();
        if (lane < nl) {
            int s = d_srcs[base + lane];
            s_s[wp][lane] = s;
            float w = expf(lrelu(d_as2[s] + ad));
            s_w[wp][lane] = w;
            den += w;
        }
        __syncwarp();
        if (lane < 25) {
            #pragma unroll 2
            for (int e = 0; e < nl; e++) {
                float w = s_w[wp][e];
                float4 v = *(const float4*)(d_h2 + (size_t)s_s[wp][e] * C2 + c4);
                acc.x += w * v.x;
                acc.y += w * v.y;
                acc.z += w * v.z;
                acc.w += w * v.w;
            }
        }
    }
    #pragma unroll
    for (int o = 16; o; o >>= 1) den += __shfl_xor_sync(0xffffffffu, den, o);
    float inv = 1.f / (den + 1e-16f);
    if (lane < 25) {
        int b = ld_idx(batch, n);
        float v;
        v = fmaxf(acc.x * inv + b2[c4], 0.f);
        atomicMax(&d_g[b * C2 + c4], __float_as_int(v));
        v = fmaxf(acc.y * inv + b2[c4 + 1], 0.f);
        atomicMax(&d_g[b * C2 + c4 + 1], __float_as_int(v));
        v = fmaxf(acc.z * inv + b2[c4 + 2], 0.f);
        atomicMax(&d_g[b * C2 + c4 + 2], __float_as_int(v));
        v = fmaxf(acc.w * inv + b2[c4 + 3], 0.f);
        atomicMax(&d_g[b * C2 + c4 + 3], __float_as_int(v));
    }
}

// ---------------- head -------------------------------------------------------
__global__ void k_final(const float* __restrict__ Wg, const float* __restrict__ bg,
                        float* __restrict__ out) {
    __shared__ float sg[C2];
    int g = blockIdx.x, t = threadIdx.x;
    if (t < C2) sg[t] = __int_as_float(d_g[g * C2 + t]);
    __syncthreads();
    if (t < C2) {
        float a = bg[t];
        #pragma unroll 4
        for (int k = 0; k < C2; k++) a += sg[k] * Wg[k * C2 + t];
        out[g * C2 + t] = fmaxf(a, 0.f);
    }
}

// ---------------- launch ------------------------------------------------------
extern "C" void kernel_launch(void* const* d_in, const int* in_sizes, int n_in,
                              void* d_out, int out_size) {
    const float* x     = (const float*)d_in[0];
    const int*   ei    = (const int*)d_in[1];
    const int*   batch = (const int*)d_in[2];

    int base = 3;
    while (base < n_in && in_sizes[base] != 78 * F1) base++;
    if (base >= n_in) base = (n_in >= 14) ? 4 : 3;

    const float* W1     = (const float*)d_in[base + 0];
    const float* a_src1 = (const float*)d_in[base + 1];
    const float* a_dst1 = (const float*)d_in[base + 2];
    const float* b1     = (const float*)d_in[base + 3];
    const float* W2     = (const float*)d_in[base + 4];
    const float* a_src2 = (const float*)d_in[base + 5];
    const float* a_dst2 = (const float*)d_in[base + 6];
    const float* b2     = (const float*)d_in[base + 7];
    const float* Wg     = (const float*)d_in[base + 8];
    const float* bg     = (const float*)d_in[base + 9];
    float* out = (float*)d_out;

    static bool s_init = false;
    static cudaStream_t s1;
    static cudaEvent_t ev0, ev1;
    if (!s_init) {
        cudaStreamCreateWithFlags(&s1, cudaStreamNonBlocking);
        cudaEventCreateWithFlags(&ev0, cudaEventDisableTiming);
        cudaEventCreateWithFlags(&ev1, cudaEventDisableTiming);
        s_init = true;
    }

    cudaEventRecord(ev0, 0);
    cudaStreamWaitEvent(s1, ev0, 0);
    k_detect <<<1, 256, 0, s1>>>(ei);
    k_zero   <<<(N_GRAPHS * C2 + 255) / 256, 256, 0, s1>>>();
    k_count  <<<(N_TOT + 255) / 256, 256, 0, s1>>>(ei);
    k_scanA  <<<20, 1024, 0, s1>>>();
    k_scanC  <<<20, 1024, 0, s1>>>();
    k_scatter<<<(N_TOT + 255) / 256, 256, 0, s1>>>(ei);
    cudaEventRecord(ev1, s1);

    k_zero0<<<(N_NODES * H1 + 255) / 256, 256>>>();      // before gemm1 atomics
    dim3 g1((N_NODES + 63) / 64, (F1P + 63) / 64);
    k_gemm1<<<g1, 256>>>(x, W1, a_src1, a_dst1);

    cudaStreamWaitEvent(0, ev1, 0);                      // join CSR before agg1
    k_agg1<<<N_NODES, 128>>>(b1);

    k_gemm2<<<(N_NODES + 63) / 64, 256>>>(W2, a_src2, a_dst2);
    k_agg2 <<<(N_NODES + 3) / 4, 128>>>(b2, batch);

    k_final<<<N_GRAPHS, 128>>>(Wg, bg, out);
}